// round 13
// baseline (speedup 1.0000x reference)
#include <cuda_runtime.h>
#include <cstdint>

#define QN 8192
#define SN 30
#define DN 512

constexpr int THREADS = 896;            // 28 warps = 7 groups of 4
constexpr int GRID    = 148;
constexpr int ROWS    = 8;              // q rows per tile
constexpr int NTILE   = QN / ROWS;      // 1024
constexpr int DQ      = 128;            // d per warp (4-way split)
constexpr int QSTRIDE = 132;            // q smem row stride: kills mma B-frag conflicts
constexpr int STRIDE  = 516;            // support smem stride: conflict-free
constexpr int GROUPS  = 7;

typedef unsigned long long ull;

__device__ __forceinline__ ull psub(ull a, ull b) {
    ull r; asm("sub.rn.f32x2 %0, %1, %2;" : "=l"(r) : "l"(a), "l"(b)); return r;
}
__device__ __forceinline__ void pfma_acc(ull& acc, ull a, ull b) {
    asm("fma.rn.f32x2 %0, %1, %2, %0;" : "+l"(acc) : "l"(a), "l"(b));
}
__device__ __forceinline__ float plo(ull a) { return __uint_as_float((unsigned)(a & 0xffffffffu)); }
__device__ __forceinline__ float phi(ull a) { return __uint_as_float((unsigned)(a >> 32)); }
__device__ __forceinline__ void cpasync16(uint32_t dst, const float* src) {
    asm volatile("cp.async.ca.shared.global [%0], [%1], 16;" :: "r"(dst), "l"(src));
}
__device__ __forceinline__ void lds128(uint32_t addr, ull& lo, ull& hi) {
    asm volatile("ld.shared.v2.b64 {%0, %1}, [%2];" : "=l"(lo), "=l"(hi) : "r"(addr));
}
// tf32 MMA: D[16x8] += A[16x8] * B[8x8] (A,B fp32 regs read as truncated tf32)
__device__ __forceinline__ void mma_tf32(float* c, uint32_t a0, uint32_t a1,
                                         uint32_t a2, uint32_t a3,
                                         uint32_t b0, uint32_t b1) {
    asm volatile(
        "mma.sync.aligned.m16n8k8.row.col.f32.tf32.tf32.f32 "
        "{%0,%1,%2,%3}, {%4,%5,%6,%7}, {%8,%9}, {%0,%1,%2,%3};"
        : "+f"(c[0]), "+f"(c[1]), "+f"(c[2]), "+f"(c[3])
        : "r"(a0), "r"(a1), "r"(a2), "r"(a3), "r"(b0), "r"(b1));
}

#define ABS2 0x7fffffff7fffffffULL

__global__ __launch_bounds__(THREADS, 1)
void resus_kernel(const float* __restrict__ qenc,
                  const float* __restrict__ senc,
                  const float* __restrict__ sy,
                  const float* __restrict__ sp,
                  const float* __restrict__ qp,
                  const float* __restrict__ w,
                  const float* __restrict__ ascale,
                  const float* __restrict__ abias,
                  const int*   __restrict__ nsamp,
                  float* __restrict__ out)
{
    extern __shared__ float sh[];
    float* sT    = sh;                   // [32][STRIDE] supports (30 real + 2 zero)
    float* wSh   = sT + 32 * STRIDE;     // [512]
    float* ssqSh = wSh + DN;             // [32] ||s||^2 per support
    float* qB    = ssqSh + 32;           // [28 warps][ROWS][QSTRIDE] staged q

    const int tid  = threadIdx.x;
    const int lane = tid & 31;
    const int warp = tid >> 5;

    const int group   = warp >> 2;       // 0..6
    const int quarter = warp & 3;        // d-quarter this warp owns
    const int tile    = blockIdx.x * GROUPS + group;
    const bool active = (tile < NTILE);

    float* qw = qB + warp * (ROWS * QSTRIDE);
    const uint32_t qwS = (uint32_t)__cvta_generic_to_shared(qw);

    // === Upfront cp.async: stage this warp's 8-row x 128-d quarter. ===
    if (active) {
        const float* qbase = qenc + (size_t)tile * ROWS * DN + quarter * DQ;
#pragma unroll
        for (int r = 0; r < ROWS; r++) {
            cpasync16(qwS + (uint32_t)((r * QSTRIDE + lane * 4) * 4),
                      qbase + (size_t)r * DN + lane * 4);
        }
        asm volatile("cp.async.commit_group;" ::: "memory");
    }

    // === Support + w staging (hides the cp.async DRAM latency). ===
    for (int idx = tid; idx < 32 * DN; idx += THREADS) {
        int s = idx >> 9, d = idx & (DN - 1);
        sT[s * STRIDE + d] = (s < SN) ? senc[idx] : 0.0f;
    }
    for (int d = tid; d < DN; d += THREADS) wSh[d] = w[d];

    // warp 0: ||s||^2 per support, straight from gmem (no ordering vs sT).
    if (warp == 0) {
        float s2 = 0.0f;
        if (lane < SN) {
            const float4* sp4 = reinterpret_cast<const float4*>(senc + (size_t)lane * DN);
#pragma unroll 8
            for (int i = 0; i < DN / 4; i++) {
                float4 v = sp4[i];
                s2 = fmaf(v.x, v.x, s2); s2 = fmaf(v.y, v.y, s2);
                s2 = fmaf(v.z, v.z, s2); s2 = fmaf(v.w, v.w, s2);
            }
        }
        ssqSh[lane] = s2;
    }

    float dyv = 0.0f;
    if (lane < SN) dyv = sy[lane] - 1.0f / (1.0f + __expf(-sp[lane]));
    const int ia = nsamp[0] - 1;
    const float scl = fabsf(ascale[ia]);
    const float bia = abias[ia];
    __syncthreads();

    if (!active) return;

    const uint32_t sBase = (uint32_t)__cvta_generic_to_shared(
                               sT + lane * STRIDE + quarter * DQ);
    const uint32_t wBase = (uint32_t)__cvta_generic_to_shared(wSh + quarter * DQ);

    asm volatile("cp.async.wait_group 0;" ::: "memory");
    __syncwarp();

    // === Hot loop: SCORE ONLY (l2 moved to tensor cores). ===
    ull aS[ROWS];
#pragma unroll
    for (int r = 0; r < ROWS; r++) aS[r] = 0;

#pragma unroll
    for (int t = 0; t < DQ / 4; t++) {
        ull svx, svy, wvx, wvy;
        lds128(sBase + t * 16, svx, svy);
        lds128(wBase + t * 16, wvx, wvy);
#pragma unroll
        for (int r = 0; r < ROWS; r++) {
            ull qx, qy;
            lds128(qwS + (uint32_t)(r * QSTRIDE * 4 + t * 16), qx, qy);
            ull d0 = psub(qx, svx);
            ull d1 = psub(qy, svy);
            pfma_acc(aS[r], d0 & ABS2, wvx);
            pfma_acc(aS[r], d1 & ABS2, wvy);
        }
    }

    // === ||q||^2 partials: lane = d-slice, per row (tiny). ===
    float qsqP[ROWS];
#pragma unroll
    for (int r = 0; r < ROWS; r++) {
        ull a, b;
        lds128(qwS + (uint32_t)((r * QSTRIDE + lane * 4) * 4), a, b);
        float x0 = plo(a), x1 = phi(a), x2 = plo(b), x3 = phi(b);
        qsqP[r] = fmaf(x0, x0, fmaf(x1, x1, fmaf(x2, x2, x3 * x3)));
    }

    // === q.s via tensor cores: C[32 s][8 rows] over this warp's 128-d slice ===
    const int gid  = lane >> 2;   // 0..7
    const int tid4 = lane & 3;    // 0..3
    float c0[4] = {0, 0, 0, 0};   // s-tile 0..15
    float c1[4] = {0, 0, 0, 0};   // s-tile 16..31
    const float* aCol = sT + quarter * DQ;

#pragma unroll
    for (int ks = 0; ks < DQ / 8; ks++) {
        const int dk = ks * 8 + tid4;
        uint32_t b0 = __float_as_uint(qw[gid * QSTRIDE + dk]);
        uint32_t b1 = __float_as_uint(qw[gid * QSTRIDE + dk + 4]);

        uint32_t a0 = __float_as_uint(aCol[(gid)      * STRIDE + dk]);
        uint32_t a1 = __float_as_uint(aCol[(gid + 8)  * STRIDE + dk]);
        uint32_t a2 = __float_as_uint(aCol[(gid)      * STRIDE + dk + 4]);
        uint32_t a3 = __float_as_uint(aCol[(gid + 8)  * STRIDE + dk + 4]);
        mma_tf32(c0, a0, a1, a2, a3, b0, b1);

        a0 = __float_as_uint(aCol[(gid + 16) * STRIDE + dk]);
        a1 = __float_as_uint(aCol[(gid + 24) * STRIDE + dk]);
        a2 = __float_as_uint(aCol[(gid + 16) * STRIDE + dk + 4]);
        a3 = __float_as_uint(aCol[(gid + 24) * STRIDE + dk + 4]);
        mma_tf32(c1, a0, a1, a2, a3, b0, b1);
    }

    // Redistribute C to (lane = s, all 8 rows) via this warp's own (now dead) qw.
    __syncwarp();
    float* cscr = qw;  // 256 floats needed, 1056 available
    cscr[(gid)      * 8 + 2 * tid4]     = c0[0];
    cscr[(gid)      * 8 + 2 * tid4 + 1] = c0[1];
    cscr[(gid + 8)  * 8 + 2 * tid4]     = c0[2];
    cscr[(gid + 8)  * 8 + 2 * tid4 + 1] = c0[3];
    cscr[(gid + 16) * 8 + 2 * tid4]     = c1[0];
    cscr[(gid + 16) * 8 + 2 * tid4 + 1] = c1[1];
    cscr[(gid + 24) * 8 + 2 * tid4]     = c1[2];
    cscr[(gid + 24) * 8 + 2 * tid4 + 1] = c1[3];
    __syncwarp();

    float dotv[ROWS];
#pragma unroll
    for (int r = 0; r < ROWS; r++) dotv[r] = cscr[lane * 8 + r];

    // === Quarter combine in the group's (dead) staging region. ===
    asm volatile("bar.sync %0, 128;" :: "r"(1 + group) : "memory");

    float4* cmb = reinterpret_cast<float4*>(qB + group * 4 * ROWS * QSTRIDE);
#pragma unroll
    for (int r = 0; r < ROWS; r++) {
        cmb[(quarter * ROWS + r) * 32 + lane] =
            make_float4(plo(aS[r]) + phi(aS[r]), dotv[r], qsqP[r], 0.0f);
    }
    asm volatile("bar.sync %0, 128;" :: "r"(1 + group) : "memory");

    // === Finalize: each warp of the group does 2 rows (lane = support). ===
#pragma unroll
    for (int k = 0; k < 2; k++) {
        const int r = quarter * 2 + k;
        float sc = 0.0f, dt = 0.0f, qq = 0.0f;
#pragma unroll
        for (int qd = 0; qd < 4; qd++) {
            float4 p = cmb[(qd * ROWS + r) * 32 + lane];
            sc += p.x; dt += p.y; qq += p.z;
        }
        // qq is a per-lane d-partial of ||q_r||^2: reduce over lanes.
#pragma unroll
        for (int d = 16; d; d >>= 1) qq += __shfl_xor_sync(0xffffffffu, qq, d);

        float l2v = 0.0f;
        if (lane < SN)
            l2v = __fsqrt_rn(fmaxf(qq + ssqSh[lane] - 2.0f * dt, 0.0f));
        else
            sc = -3.4e38f;

        float m = sc;
#pragma unroll
        for (int d = 16; d; d >>= 1) m = fmaxf(m, __shfl_xor_sync(0xffffffffu, m, d));
        float e  = __expf(sc - m);
        float se = e, sd = e * dyv, sl = l2v;
#pragma unroll
        for (int d = 16; d; d >>= 1) {
            se += __shfl_xor_sync(0xffffffffu, se, d);
            sd += __shfl_xor_sync(0xffffffffu, sd, d);
            sl += __shfl_xor_sync(0xffffffffu, sl, d);
        }
        if (lane == 0) {
            const int row = tile * ROWS + r;
            out[row]      = (sd / se) * scl + bia + qp[row];
            out[QN + row] = sl * (1.0f / (float)SN);
        }
    }
}

extern "C" void kernel_launch(void* const* d_in, const int* in_sizes, int n_in,
                              void* d_out, int out_size) {
    const float* qenc   = (const float*)d_in[0];
    const float* senc   = (const float*)d_in[1];
    const float* sy     = (const float*)d_in[2];
    const float* sp     = (const float*)d_in[3];
    const float* qp     = (const float*)d_in[4];
    const float* w      = (const float*)d_in[5];
    // d_in[6] = fc1_b (softmax-invariant, unused)
    const float* ascale = (const float*)d_in[7];
    const float* abias  = (const float*)d_in[8];
    const int*   nsamp  = (const int*)d_in[9];

    float* out = (float*)d_out;

    // smem floats: supports 32*516 + w 512 + ssq 32 + qStage 28*8*132
    const int smemFloats = 32 * STRIDE + DN + 32 + 28 * ROWS * QSTRIDE;
    const int smemBytes = smemFloats * (int)sizeof(float); // ~186 KB
    cudaFuncSetAttribute(resus_kernel,
                         cudaFuncAttributeMaxDynamicSharedMemorySize, smemBytes);

    resus_kernel<<<GRID, THREADS, smemBytes>>>(qenc, senc, sy, sp, qp, w,
                                               ascale, abias, nsamp, out);
}

// round 14
// speedup vs baseline: 1.2354x; 1.2354x over previous
#include <cuda_runtime.h>
#include <cstdint>

#define QN 8192
#define SN 30
#define DN 512

constexpr int THREADS = 896;            // 28 warps = 7 groups of 4
constexpr int GRID    = 148;
constexpr int ROWS    = 8;              // q rows per tile
constexpr int NTILE   = QN / ROWS;      // 1024
constexpr int DQ      = 128;            // d per warp (4-way split)
constexpr int STRIDE  = 516;            // support smem stride (floats): conflict-free
constexpr int GROUPS  = 7;

typedef unsigned long long ull;

__device__ __forceinline__ ull psub(ull a, ull b) {
    ull r; asm("sub.rn.f32x2 %0, %1, %2;" : "=l"(r) : "l"(a), "l"(b)); return r;
}
__device__ __forceinline__ void pfma_acc(ull& acc, ull a, ull b) {
    asm("fma.rn.f32x2 %0, %1, %2, %0;" : "+l"(acc) : "l"(a), "l"(b));
}
__device__ __forceinline__ float plo(ull a) { return __uint_as_float((unsigned)(a & 0xffffffffu)); }
__device__ __forceinline__ float phi(ull a) { return __uint_as_float((unsigned)(a >> 32)); }
__device__ __forceinline__ void cpasync16(uint32_t dst, const float* src) {
    asm volatile("cp.async.ca.shared.global [%0], [%1], 16;" :: "r"(dst), "l"(src));
}
__device__ __forceinline__ void lds128(uint32_t addr, ull& lo, ull& hi) {
    asm volatile("ld.shared.v2.b64 {%0, %1}, [%2];" : "=l"(lo), "=l"(hi) : "r"(addr));
}

#define ABS2 0x7fffffff7fffffffULL

__global__ __launch_bounds__(THREADS, 1)
void resus_kernel(const float* __restrict__ qenc,
                  const float* __restrict__ senc,
                  const float* __restrict__ sy,
                  const float* __restrict__ sp,
                  const float* __restrict__ qp,
                  const float* __restrict__ w,
                  const float* __restrict__ ascale,
                  const float* __restrict__ abias,
                  const int*   __restrict__ nsamp,
                  float* __restrict__ out)
{
    extern __shared__ float sh[];
    float* sT  = sh;                 // [32][STRIDE] supports (30 real + 2 zero)
    float* wSh = sT + 32 * STRIDE;   // [512]
    float* qB  = wSh + DN;           // [28 warps][ROWS][DQ] staged q (4 KB/warp)

    const int tid  = threadIdx.x;
    const int lane = tid & 31;
    const int warp = tid >> 5;

    const int group   = warp >> 2;       // 0..6
    const int quarter = warp & 3;        // d-quarter this warp owns
    const int tile    = blockIdx.x * GROUPS + group;
    const bool active = (tile < NTILE);

    float* qw = qB + warp * (ROWS * DQ);
    const uint32_t qwS = (uint32_t)__cvta_generic_to_shared(qw);
    const uint32_t sTS = (uint32_t)__cvta_generic_to_shared(sT);
    const uint32_t wSS = (uint32_t)__cvta_generic_to_shared(wSh);

    // === ALL staging via fire-and-forget cp.async: one DRAM round-trip total
    // instead of ~18 serialized LDG->STS dependencies per thread. ===

    // q tile: this warp's 8-row x 128-d quarter (8 ops).
    if (active) {
        const float* qbase = qenc + (size_t)tile * ROWS * DN + quarter * DQ;
#pragma unroll
        for (int r = 0; r < ROWS; r++) {
            cpasync16(qwS + (uint32_t)((r * DQ + lane * 4) * 4),
                      qbase + (size_t)r * DN + lane * 4);
        }
    }

    // supports: 30 rows x 512 floats = 3840 16B-chunks across 896 threads.
#pragma unroll
    for (int k = 0; k < 5; k++) {
        int idx = tid + k * THREADS;
        if (idx < (SN * DN) / 4) {
            int s = idx >> 7;            // 0..29
            int c = (idx & 127) * 4;     // float offset within row
            cpasync16(sTS + (uint32_t)((s * STRIDE + c) * 4),
                      senc + (size_t)s * DN + c);
        }
    }
    // w: 128 chunks.
    if (tid < DN / 4) cpasync16(wSS + (uint32_t)(tid * 16), w + tid * 4);

    asm volatile("cp.async.commit_group;" ::: "memory");

    // Zero pad rows 30,31 (plain STS, visible after __syncthreads).
    if (tid < STRIDE) {
        sT[30 * STRIDE + tid] = 0.0f;
        sT[31 * STRIDE + tid] = 0.0f;
    }

    // Per-lane constants (independent gmem, overlaps the cp.async round-trip).
    float dyv = 0.0f;
    if (lane < SN) dyv = sy[lane] - 1.0f / (1.0f + __expf(-sp[lane]));
    const int ia = nsamp[0] - 1;
    const float scl = fabsf(ascale[ia]);
    const float bia = abias[ia];

    asm volatile("cp.async.wait_group 0;" ::: "memory");
    __syncthreads();

    if (!active) return;

    const uint32_t sBase = (uint32_t)__cvta_generic_to_shared(
                               sT + lane * STRIDE + quarter * DQ);
    const uint32_t wBase = (uint32_t)__cvta_generic_to_shared(wSh + quarter * DQ);

    ull aS[ROWS], aL[ROWS];
#pragma unroll
    for (int r = 0; r < ROWS; r++) { aS[r] = 0; aL[r] = 0; }

    // === Hot loop: 32 sub-iters x (10 LDS.128 + packed math), fully unrolled. ===
#pragma unroll
    for (int t = 0; t < DQ / 4; t++) {
        ull svx, svy, wvx, wvy;
        lds128(sBase + t * 16, svx, svy);   // lane-strided: conflict-free phases
        lds128(wBase + t * 16, wvx, wvy);   // broadcast
#pragma unroll
        for (int r = 0; r < ROWS; r++) {
            ull qx, qy;
            lds128(qwS + (uint32_t)(r * DQ * 4 + t * 16), qx, qy);  // broadcast
            ull d0 = psub(qx, svx);
            ull d1 = psub(qy, svy);
            pfma_acc(aL[r], d0, d0);
            pfma_acc(aL[r], d1, d1);
            pfma_acc(aS[r], d0 & ABS2, wvx);
            pfma_acc(aS[r], d1 & ABS2, wvy);
        }
    }

    // === Quarter combine: barrier -> write into dead staging region -> barrier.
    asm volatile("bar.sync %0, 128;" :: "r"(1 + group) : "memory");

    float2* cmb = reinterpret_cast<float2*>(qB + group * 4 * ROWS * DQ);
#pragma unroll
    for (int r = 0; r < ROWS; r++) {
        cmb[(quarter * ROWS + r) * 32 + lane] =
            make_float2(plo(aS[r]) + phi(aS[r]), plo(aL[r]) + phi(aL[r]));
    }
    asm volatile("bar.sync %0, 128;" :: "r"(1 + group) : "memory");

    // Each warp of the group finalizes 2 rows (lane = support).
#pragma unroll
    for (int k = 0; k < 2; k++) {
        const int r = quarter * 2 + k;
        float sc = 0.0f, ssq = 0.0f;
#pragma unroll
        for (int qd = 0; qd < 4; qd++) {
            float2 p = cmb[(qd * ROWS + r) * 32 + lane];
            sc += p.x; ssq += p.y;
        }
        float l2v = __fsqrt_rn(ssq);
        if (lane >= SN) { sc = -3.4e38f; l2v = 0.0f; }

        float m = sc;
#pragma unroll
        for (int d = 16; d; d >>= 1) m = fmaxf(m, __shfl_xor_sync(0xffffffffu, m, d));
        float e  = __expf(sc - m);
        float se = e, sd = e * dyv, sl = l2v;
#pragma unroll
        for (int d = 16; d; d >>= 1) {
            se += __shfl_xor_sync(0xffffffffu, se, d);
            sd += __shfl_xor_sync(0xffffffffu, sd, d);
            sl += __shfl_xor_sync(0xffffffffu, sl, d);
        }
        if (lane == 0) {
            const int row = tile * ROWS + r;
            out[row]      = (sd / se) * scl + bia + qp[row];
            out[QN + row] = sl * (1.0f / (float)SN);
        }
    }
}

extern "C" void kernel_launch(void* const* d_in, const int* in_sizes, int n_in,
                              void* d_out, int out_size) {
    const float* qenc   = (const float*)d_in[0];
    const float* senc   = (const float*)d_in[1];
    const float* sy     = (const float*)d_in[2];
    const float* sp     = (const float*)d_in[3];
    const float* qp     = (const float*)d_in[4];
    const float* w      = (const float*)d_in[5];
    // d_in[6] = fc1_b (softmax-invariant, unused)
    const float* ascale = (const float*)d_in[7];
    const float* abias  = (const float*)d_in[8];
    const int*   nsamp  = (const int*)d_in[9];

    float* out = (float*)d_out;

    // smem floats: supports 32*516 + w 512 + qStage 28*8*128
    const int smemFloats = 32 * STRIDE + DN + 28 * ROWS * DQ;
    const int smemBytes = smemFloats * (int)sizeof(float); // ~183 KB
    cudaFuncSetAttribute(resus_kernel,
                         cudaFuncAttributeMaxDynamicSharedMemorySize, smemBytes);

    resus_kernel<<<GRID, THREADS, smemBytes>>>(qenc, senc, sy, sp, qp, w,
                                               ascale, abias, nsamp, out);
}

// round 17
// speedup vs baseline: 1.2465x; 1.0089x over previous
#include <cuda_runtime.h>
#include <cstdint>

#define QN 8192
#define SN 30
#define DN 512

constexpr int THREADS = 896;            // 28 warps = 7 groups of 4
constexpr int GRID    = 148;
constexpr int ROWS    = 8;              // q rows per tile
constexpr int NTILE   = QN / ROWS;      // 1024
constexpr int DQ      = 128;            // d per warp (4-way split)
constexpr int QSTRIDE = 132;            // q smem row stride: conflict-free mma B-frags
constexpr int STRIDE  = 516;            // support smem stride: conflict-free
constexpr int GROUPS  = 7;

typedef unsigned long long ull;

__device__ __forceinline__ ull psub(ull a, ull b) {
    ull r; asm("sub.rn.f32x2 %0, %1, %2;" : "=l"(r) : "l"(a), "l"(b)); return r;
}
__device__ __forceinline__ void pfma_acc(ull& acc, ull a, ull b) {
    asm("fma.rn.f32x2 %0, %1, %2, %0;" : "+l"(acc) : "l"(a), "l"(b));
}
__device__ __forceinline__ float plo(ull a) { return __uint_as_float((unsigned)(a & 0xffffffffu)); }
__device__ __forceinline__ float phi(ull a) { return __uint_as_float((unsigned)(a >> 32)); }
__device__ __forceinline__ void cpasync16(uint32_t dst, const float* src) {
    asm volatile("cp.async.ca.shared.global [%0], [%1], 16;" :: "r"(dst), "l"(src));
}
__device__ __forceinline__ void lds128(uint32_t addr, ull& lo, ull& hi) {
    asm volatile("ld.shared.v2.b64 {%0, %1}, [%2];" : "=l"(lo), "=l"(hi) : "r"(addr));
}
__device__ __forceinline__ void mma_tf32(float* c, uint32_t a0, uint32_t a1,
                                         uint32_t a2, uint32_t a3,
                                         uint32_t b0, uint32_t b1) {
    asm volatile(
        "mma.sync.aligned.m16n8k8.row.col.f32.tf32.tf32.f32 "
        "{%0,%1,%2,%3}, {%4,%5,%6,%7}, {%8,%9}, {%0,%1,%2,%3};"
        : "+f"(c[0]), "+f"(c[1]), "+f"(c[2]), "+f"(c[3])
        : "r"(a0), "r"(a1), "r"(a2), "r"(a3), "r"(b0), "r"(b1));
}

#define ABS2 0x7fffffff7fffffffULL

__global__ __launch_bounds__(THREADS, 1)
void resus_kernel(const float* __restrict__ qenc,
                  const float* __restrict__ senc,
                  const float* __restrict__ sy,
                  const float* __restrict__ sp,
                  const float* __restrict__ qp,
                  const float* __restrict__ w,
                  const float* __restrict__ ascale,
                  const float* __restrict__ abias,
                  const int*   __restrict__ nsamp,
                  float* __restrict__ out)
{
    extern __shared__ float sh[];
    float* sT    = sh;                   // [32][STRIDE] supports (30 real + 2 zero)
    float* wSh   = sT + 32 * STRIDE;     // [512]
    float* ssqSh = wSh + DN;             // [32] ||s||^2
    float* qB    = ssqSh + 32;           // [28 warps][ROWS][QSTRIDE] staged q

    const int tid  = threadIdx.x;
    const int lane = tid & 31;
    const int warp = tid >> 5;

    const int group   = warp >> 2;
    const int quarter = warp & 3;
    const int tile    = blockIdx.x * GROUPS + group;
    const bool active = (tile < NTILE);

    float* qw = qB + warp * (ROWS * QSTRIDE);
    const uint32_t qwS = (uint32_t)__cvta_generic_to_shared(qw);
    const uint32_t sTS = (uint32_t)__cvta_generic_to_shared(sT);
    const uint32_t wSS = (uint32_t)__cvta_generic_to_shared(wSh);

    // === Fire-and-forget cp.async staging (R14): one DRAM round-trip. ===
    if (active) {
        const float* qbase = qenc + (size_t)tile * ROWS * DN + quarter * DQ;
#pragma unroll
        for (int r = 0; r < ROWS; r++) {
            cpasync16(qwS + (uint32_t)((r * QSTRIDE + lane * 4) * 4),
                      qbase + (size_t)r * DN + lane * 4);
        }
    }
#pragma unroll
    for (int k = 0; k < 5; k++) {
        int idx = tid + k * THREADS;
        if (idx < (SN * DN) / 4) {
            int s = idx >> 7;
            int c = (idx & 127) * 4;
            cpasync16(sTS + (uint32_t)((s * STRIDE + c) * 4),
                      senc + (size_t)s * DN + c);
        }
    }
    if (tid < DN / 4) cpasync16(wSS + (uint32_t)(tid * 16), w + tid * 4);
    asm volatile("cp.async.commit_group;" ::: "memory");

    if (tid < STRIDE) {
        sT[30 * STRIDE + tid] = 0.0f;
        sT[31 * STRIDE + tid] = 0.0f;
    }

    float dyv = 0.0f;
    if (lane < SN) dyv = sy[lane] - 1.0f / (1.0f + __expf(-sp[lane]));
    const int ia = nsamp[0] - 1;
    const float scl = fabsf(ascale[ia]);
    const float bia = abias[ia];

    asm volatile("cp.async.wait_group 0;" ::: "memory");
    __syncthreads();

    // === ||s||^2 from smem, all warps in parallel (warp w -> rows w, w+28). ===
    {
        int s = warp;
#pragma unroll
        for (int pass = 0; pass < 2; pass++) {
            if (s < 32) {
                float acc = 0.0f;
                const uint32_t rb = sTS + (uint32_t)(s * STRIDE * 4);
#pragma unroll
                for (int i = 0; i < 4; i++) {
                    ull a, b;
                    lds128(rb + (uint32_t)((lane * 4 + i * 128) * 4), a, b);
                    float x0 = plo(a), x1 = phi(a), x2 = plo(b), x3 = phi(b);
                    acc = fmaf(x0, x0, fmaf(x1, x1, fmaf(x2, x2, fmaf(x3, x3, acc))));
                }
#pragma unroll
                for (int d = 16; d; d >>= 1)
                    acc += __shfl_xor_sync(0xffffffffu, acc, d);
                if (lane == 0) ssqSh[s] = acc;
            }
            s = warp + 28;
        }
    }
    __syncthreads();

    if (!active) return;

    const uint32_t sBase = sTS + (uint32_t)((lane * STRIDE + quarter * DQ) * 4);
    const uint32_t wBase = wSS + (uint32_t)(quarter * DQ * 4);

    // === Hot loop: SCORE ONLY (Σd² offloaded to tensor cores). ===
    ull aS[ROWS];
#pragma unroll
    for (int r = 0; r < ROWS; r++) aS[r] = 0;

#pragma unroll
    for (int t = 0; t < DQ / 4; t++) {
        ull svx, svy, wvx, wvy;
        lds128(sBase + t * 16, svx, svy);
        lds128(wBase + t * 16, wvx, wvy);
#pragma unroll
        for (int r = 0; r < ROWS; r++) {
            ull qx, qy;
            lds128(qwS + (uint32_t)((r * QSTRIDE + t * 4) * 4), qx, qy);
            ull d0 = psub(qx, svx);
            ull d1 = psub(qy, svy);
            pfma_acc(aS[r], d0 & ABS2, wvx);
            pfma_acc(aS[r], d1 & ABS2, wvy);
        }
    }

    // === ||q||^2 partials: lane = 16B d-slice of this quarter, per row. ===
    float qsqP[ROWS];
#pragma unroll
    for (int r = 0; r < ROWS; r++) {
        ull a, b;
        lds128(qwS + (uint32_t)((r * QSTRIDE + lane * 4) * 4), a, b);
        float x0 = plo(a), x1 = phi(a), x2 = plo(b), x3 = phi(b);
        qsqP[r] = fmaf(x0, x0, fmaf(x1, x1, fmaf(x2, x2, x3 * x3)));
    }

    // === q.s on tensor cores: C[32 s][8 rows] over this warp's 128-d slice.
    // Fragment mapping verified in R13. ===
    const int gid  = lane >> 2;
    const int tid4 = lane & 3;
    float c0[4] = {0, 0, 0, 0};
    float c1[4] = {0, 0, 0, 0};
    const float* aCol = sT + quarter * DQ;

#pragma unroll 4
    for (int ks = 0; ks < DQ / 8; ks++) {
        const int dk = ks * 8 + tid4;
        uint32_t b0 = __float_as_uint(qw[gid * QSTRIDE + dk]);
        uint32_t b1 = __float_as_uint(qw[gid * QSTRIDE + dk + 4]);

        uint32_t a0 = __float_as_uint(aCol[(gid)      * STRIDE + dk]);
        uint32_t a1 = __float_as_uint(aCol[(gid + 8)  * STRIDE + dk]);
        uint32_t a2 = __float_as_uint(aCol[(gid)      * STRIDE + dk + 4]);
        uint32_t a3 = __float_as_uint(aCol[(gid + 8)  * STRIDE + dk + 4]);
        mma_tf32(c0, a0, a1, a2, a3, b0, b1);

        a0 = __float_as_uint(aCol[(gid + 16) * STRIDE + dk]);
        a1 = __float_as_uint(aCol[(gid + 24) * STRIDE + dk]);
        a2 = __float_as_uint(aCol[(gid + 16) * STRIDE + dk + 4]);
        a3 = __float_as_uint(aCol[(gid + 24) * STRIDE + dk + 4]);
        mma_tf32(c1, a0, a1, a2, a3, b0, b1);
    }

    // Redistribute C via this warp's own (now dead) qw: (lane=s, col=row).
    __syncwarp();
    float* cscr = qw;
    cscr[(gid)      * 8 + 2 * tid4]     = c0[0];
    cscr[(gid)      * 8 + 2 * tid4 + 1] = c0[1];
    cscr[(gid + 8)  * 8 + 2 * tid4]     = c0[2];
    cscr[(gid + 8)  * 8 + 2 * tid4 + 1] = c0[3];
    cscr[(gid + 16) * 8 + 2 * tid4]     = c1[0];
    cscr[(gid + 16) * 8 + 2 * tid4 + 1] = c1[1];
    cscr[(gid + 24) * 8 + 2 * tid4]     = c1[2];
    cscr[(gid + 24) * 8 + 2 * tid4 + 1] = c1[3];
    __syncwarp();

    // CRITICAL (R16 bug): pull dot values into REGISTERS before cmb writes —
    // cmb aliases the group's staging regions, including this warp's cscr.
    float dotv[ROWS];
#pragma unroll
    for (int r = 0; r < ROWS; r++) dotv[r] = cscr[lane * 8 + r];

    // === Quarter combine: barrier -> write into dead group staging -> barrier.
    asm volatile("bar.sync %0, 128;" :: "r"(1 + group) : "memory");

    float4* cmb = reinterpret_cast<float4*>(qB + group * 4 * ROWS * QSTRIDE);
#pragma unroll
    for (int r = 0; r < ROWS; r++) {
        cmb[(quarter * ROWS + r) * 32 + lane] =
            make_float4(plo(aS[r]) + phi(aS[r]), dotv[r], qsqP[r], 0.0f);
    }
    asm volatile("bar.sync %0, 128;" :: "r"(1 + group) : "memory");

    // === Finalize: each warp of the group does 2 rows (lane = support). ===
#pragma unroll
    for (int k = 0; k < 2; k++) {
        const int r = quarter * 2 + k;
        float sc = 0.0f, dt = 0.0f, qq = 0.0f;
#pragma unroll
        for (int qd = 0; qd < 4; qd++) {
            float4 p = cmb[(qd * ROWS + r) * 32 + lane];
            sc += p.x; dt += p.y; qq += p.z;
        }
#pragma unroll
        for (int d = 16; d; d >>= 1) qq += __shfl_xor_sync(0xffffffffu, qq, d);

        float l2v = 0.0f;
        if (lane < SN)
            l2v = __fsqrt_rn(fmaxf(qq + ssqSh[lane] - 2.0f * dt, 0.0f));
        else
            sc = -3.4e38f;

        float m = sc;
#pragma unroll
        for (int d = 16; d; d >>= 1) m = fmaxf(m, __shfl_xor_sync(0xffffffffu, m, d));
        float e  = __expf(sc - m);
        float se = e, sd = e * dyv, sl = l2v;
#pragma unroll
        for (int d = 16; d; d >>= 1) {
            se += __shfl_xor_sync(0xffffffffu, se, d);
            sd += __shfl_xor_sync(0xffffffffu, sd, d);
            sl += __shfl_xor_sync(0xffffffffu, sl, d);
        }
        if (lane == 0) {
            const int row = tile * ROWS + r;
            out[row]      = (sd / se) * scl + bia + qp[row];
            out[QN + row] = sl * (1.0f / (float)SN);
        }
    }
}

extern "C" void kernel_launch(void* const* d_in, const int* in_sizes, int n_in,
                              void* d_out, int out_size) {
    const float* qenc   = (const float*)d_in[0];
    const float* senc   = (const float*)d_in[1];
    const float* sy     = (const float*)d_in[2];
    const float* sp     = (const float*)d_in[3];
    const float* qp     = (const float*)d_in[4];
    const float* w      = (const float*)d_in[5];
    // d_in[6] = fc1_b (softmax-invariant, unused)
    const float* ascale = (const float*)d_in[7];
    const float* abias  = (const float*)d_in[8];
    const int*   nsamp  = (const int*)d_in[9];

    float* out = (float*)d_out;

    // smem floats: supports 32*516 + w 512 + ssq 32 + qStage 28*8*132
    const int smemFloats = 32 * STRIDE + DN + 32 + 28 * ROWS * QSTRIDE;
    const int smemBytes = smemFloats * (int)sizeof(float); // ~186 KB
    cudaFuncSetAttribute(resus_kernel,
                         cudaFuncAttributeMaxDynamicSharedMemorySize, smemBytes);

    resus_kernel<<<GRID, THREADS, smemBytes>>>(qenc, senc, sy, sp, qp, w,
                                               ascale, abias, nsamp, out);
}